// round 3
// baseline (speedup 1.0000x reference)
#include <cuda_runtime.h>

// ---------------------------------------------------------------------------
// VirtualTextureModule: trilinear mip-mapped texture sampling (wrap mode).
//  data: [1,4096,4096,3] f32, texc: [1,1024,1024,2], texc_deriv: [1,1024,1024,4]
//  out:  [1,1024,1024,3] f32
//
// Pipeline:
//   1) build mip levels 1..8 via 2x2 box filter into g_mips scratch
//   2) per output pixel: lod from UV derivatives -> lerp of bilinear(wrap)
//      samples from levels floor(lod) and floor(lod)+1  (exact: reference's
//      per-level weight clip(1-|lod-l|,0,1) is nonzero for at most 2 levels)
// ---------------------------------------------------------------------------

#define BASE_W   4096
#define OUT_W    1024
#define MAX_MIP  8

// Scratch for mip levels 1..8 (sum of (4096>>l)^2 * 3, l=1..8) = 16,776,960 floats
__device__ float g_mips[16776960];

// Offsets of levels 1..8 within g_mips (index 0 unused: level 0 = input data)
__constant__ int c_mip_off[9] = {
    0,          // level 0 (unused; lives in input buffer)
    0,          // level 1: 2048^2*3 = 12,582,912
    12582912,   // level 2: 1024^2*3 =  3,145,728
    15728640,   // level 3:  512^2*3 =    786,432
    16515072,   // level 4:  256^2*3 =    196,608
    16711680,   // level 5:  128^2*3 =     49,152
    16760832,   // level 6:   64^2*3 =     12,288
    16773120,   // level 7:   32^2*3 =      3,072
    16776192    // level 8:   16^2*3 =        768
};

// ---------------------------------------------------------------------------
// 2x2 box-filter downsample, vectorized: one thread per 4 consecutive output
// texels. Per input row it reads 6 aligned float4 (8 input texels * RGB),
// writes 3 aligned float4. in_off/out_off are float offsets into g_mips;
// in_off < 0 means "read from the base texture pointer instead".
// ---------------------------------------------------------------------------
__global__ void mip_down4(const float* __restrict__ base,
                          int in_off, int out_off,
                          int wq /* w_out/4 */, int shift_q /* log2(wq) */)
{
    int idx = blockIdx.x * blockDim.x + threadIdx.x;
    int n = wq * (wq << 2);              // (w_out/4) * w_out thread count
    if (idx >= n) return;
    int xg = idx & (wq - 1);             // group of 4 output texels
    int y  = idx >> shift_q;
    int w_out = wq << 2;
    int w_in  = w_out << 1;

    const float* in = (in_off < 0) ? base : (g_mips + in_off);
    // float offset of first input texel: (2y * w_in + 8*xg) * 3
    int base_f = 6 * w_in * y + 24 * xg;         // multiple of 4
    const float4* r0 = (const float4*)(in + base_f);
    const float4* r1 = (const float4*)(in + base_f + 3 * w_in);

    float s[24];
#pragma unroll
    for (int i = 0; i < 6; i++) {
        float4 a = r0[i];
        float4 b = r1[i];
        s[4 * i + 0] = a.x + b.x;
        s[4 * i + 1] = a.y + b.y;
        s[4 * i + 2] = a.z + b.z;
        s[4 * i + 3] = a.w + b.w;
    }

    float o[12];
#pragma unroll
    for (int j = 0; j < 4; j++) {
#pragma unroll
        for (int c = 0; c < 3; c++) {
            o[3 * j + c] = 0.25f * (s[6 * j + c] + s[6 * j + 3 + c]);
        }
    }

    float4* op = (float4*)(g_mips + out_off + 12 * idx);
#pragma unroll
    for (int i = 0; i < 3; i++) {
        op[i] = make_float4(o[4 * i], o[4 * i + 1], o[4 * i + 2], o[4 * i + 3]);
    }
}

// ---------------------------------------------------------------------------
// Bilinear sample with wrap addressing on a square power-of-two level.
// ---------------------------------------------------------------------------
struct F3 { float x, y, z; };

__device__ __forceinline__ F3 bilin_wrap(const float* __restrict__ t, int w,
                                         float u, float v)
{
    float xs = u * (float)w - 0.5f;
    float ys = v * (float)w - 0.5f;
    float xf = floorf(xs);
    float yf = floorf(ys);
    float fx = xs - xf;
    float fy = ys - yf;
    int m = w - 1;
    int x0 = ((int)xf) & m;          // two's-complement AND handles -1 wrap
    int y0 = ((int)yf) & m;
    int x1 = (x0 + 1) & m;
    int y1 = (y0 + 1) & m;

    const float* p00 = t + ((size_t)y0 * w + x0) * 3;
    const float* p01 = t + ((size_t)y0 * w + x1) * 3;
    const float* p10 = t + ((size_t)y1 * w + x0) * 3;
    const float* p11 = t + ((size_t)y1 * w + x1) * 3;

    F3 r;
#pragma unroll
    for (int c = 0; c < 3; c++) {
        float top = p00[c] + fx * (p01[c] - p00[c]);
        float bot = p10[c] + fx * (p11[c] - p10[c]);
        float val = top + fy * (bot - top);
        if (c == 0) r.x = val; else if (c == 1) r.y = val; else r.z = val;
    }
    return r;
}

// ---------------------------------------------------------------------------
// Main sample pass: one thread per output pixel.
// ---------------------------------------------------------------------------
__global__ void vt_sample(const float* __restrict__ base,
                          const float2* __restrict__ texc,
                          const float4* __restrict__ deriv,
                          float* __restrict__ out)
{
    int idx = blockIdx.x * blockDim.x + threadIdx.x;
    if (idx >= OUT_W * OUT_W) return;

    float4 d = deriv[idx];
    float dudx = d.x * (float)BASE_W;
    float dvdx = d.y * (float)BASE_W;
    float dudy = d.z * (float)BASE_W;
    float dvdy = d.w * (float)BASE_W;
    float rho2 = fmaxf(dudx * dudx + dvdx * dvdx, dudy * dudy + dvdy * dvdy);
    float lod = 0.5f * __log2f(fmaxf(rho2, 1e-20f));
    lod = fminf(fmaxf(lod, 0.0f), (float)MAX_MIP);

    int l0 = min((int)lod, MAX_MIP);
    float fr = lod - (float)l0;
    int l1 = min(l0 + 1, MAX_MIP);

    float2 uv = texc[idx];

    const float* t0 = (l0 == 0) ? base : (g_mips + c_mip_off[l0]);
    F3 a = bilin_wrap(t0, BASE_W >> l0, uv.x, uv.y);

    const float* t1 = (l1 == 0) ? base : (g_mips + c_mip_off[l1]);
    F3 b = bilin_wrap(t1, BASE_W >> l1, uv.x, uv.y);

    float* o = out + (size_t)idx * 3;
    o[0] = a.x + fr * (b.x - a.x);
    o[1] = a.y + fr * (b.y - a.y);
    o[2] = a.z + fr * (b.z - a.z);
}

// ---------------------------------------------------------------------------
extern "C" void kernel_launch(void* const* d_in, const int* in_sizes, int n_in,
                              void* d_out, int out_size)
{
    const float*  data  = (const float*)d_in[0];
    const float2* texc  = (const float2*)d_in[1];
    const float4* deriv = (const float4*)d_in[2];
    float* out = (float*)d_out;

    static const int off_h[9] = {
        0, 0, 12582912, 15728640, 16515072, 16711680, 16760832, 16773120, 16776192
    };

    const int TPB = 256;

    // Levels 1..8: level 1 reads base (in_off = -1), rest read g_mips.
    int w = BASE_W >> 1;                   // 2048
    int shift = 11;
    for (int l = 1; l <= MAX_MIP; l++) {
        int wq = w >> 2;
        int n = wq * w;                    // threads: 4 texels each
        int in_off = (l == 1) ? -1 : off_h[l - 1];
        mip_down4<<<(n + TPB - 1) / TPB, TPB>>>(data, in_off, off_h[l],
                                                wq, shift - 2);
        w >>= 1;
        shift--;
    }

    // Sample pass
    {
        int n = OUT_W * OUT_W;
        vt_sample<<<(n + TPB - 1) / TPB, TPB>>>(data, texc, deriv, out);
    }
}

// round 4
// speedup vs baseline: 1.2469x; 1.2469x over previous
#include <cuda_runtime.h>

// ---------------------------------------------------------------------------
// VirtualTextureModule: trilinear mip-mapped texture sampling (wrap mode).
//  data: [1,4096,4096,3] f32, texc: [1,1024,1024,2], texc_deriv: [1,1024,1024,4]
//  out:  [1,1024,1024,3] f32
//
// R4: fused mip-chain build. 3 levels per kernel (one thread = one deepest-
// level texel from an 8x8 input region, writing all intermediate levels).
// 9 launches -> 4 launches; removes level-1/level-3 re-read (~53 MB HBM).
// ---------------------------------------------------------------------------

#define BASE_W   4096
#define OUT_W    1024
#define MAX_MIP  8

// Scratch for mip levels 1..8 (sum of (4096>>l)^2 * 3, l=1..8) = 16,776,960 floats
__device__ float g_mips[16776960];

// Offsets of levels 1..8 within g_mips (index 0 unused: level 0 = input data)
__constant__ int c_mip_off[9] = {
    0,          // level 0 (unused; lives in input buffer)
    0,          // level 1: 2048^2*3 = 12,582,912
    12582912,   // level 2: 1024^2*3 =  3,145,728
    15728640,   // level 3:  512^2*3 =    786,432
    16515072,   // level 4:  256^2*3 =    196,608
    16711680,   // level 5:  128^2*3 =     49,152
    16760832,   // level 6:   64^2*3 =     12,288
    16773120,   // level 7:   32^2*3 =      3,072
    16776192    // level 8:   16^2*3 =        768
};

// ---------------------------------------------------------------------------
// Fused 3-level 2x2 box-filter downsample.
// One thread = one level-(l+3) texel, built from an 8x8 region of level l.
// Writes level l+1 (float4), level l+2 (float2), level l+3 (scalar).
// in_off < 0 -> read base texture; else read g_mips + in_off.
// w_in = input level width; w_c = w_in/8; shift_c = log2(w_c).
// ---------------------------------------------------------------------------
__global__ void mip3(const float* __restrict__ base, int in_off,
                     int off_a, int off_b, int off_c,
                     int w_in, int shift_c)
{
    int w_c = w_in >> 3;
    int n = w_c * w_c;
    int idx = blockIdx.x * blockDim.x + threadIdx.x;
    if (idx >= n) return;
    int xc = idx & (w_c - 1);
    int yc = idx >> shift_c;

    const float* in = (in_off < 0) ? base : (g_mips + in_off);
    int rs_in = 3 * w_in;                 // float stride of one input row
    int w_a = w_in >> 1;
    int w_b = w_in >> 2;

    float acc2[6];                        // level-(l+2) partial (2 x-texels)
    float acc3[3] = {0.f, 0.f, 0.f};      // level-(l+3) accumulator

#pragma unroll
    for (int p = 0; p < 4; p++) {         // 4 row-pairs of the 8x8 region
        const float4* r0 = (const float4*)(in + (8 * yc + 2 * p) * rs_in + 24 * xc);
        const float4* r1 = (const float4*)((const float*)r0 + rs_in);

        float s[24];
#pragma unroll
        for (int i = 0; i < 6; i++) {
            float4 a = r0[i];
            float4 b = r1[i];
            s[4 * i + 0] = a.x + b.x;
            s[4 * i + 1] = a.y + b.y;
            s[4 * i + 2] = a.z + b.z;
            s[4 * i + 3] = a.w + b.w;
        }

        // 4 level-(l+1) texels along x
        float l1[12];
#pragma unroll
        for (int j = 0; j < 4; j++)
#pragma unroll
            for (int c = 0; c < 3; c++)
                l1[3 * j + c] = 0.25f * (s[6 * j + c] + s[6 * j + 3 + c]);

        // write level l+1 row (4*yc+p), cols 4*xc..4*xc+3  (3 float4, aligned)
        {
            float4* oa = (float4*)(g_mips + off_a + ((4 * yc + p) * w_a + 4 * xc) * 3);
#pragma unroll
            for (int i = 0; i < 3; i++)
                oa[i] = make_float4(l1[4 * i], l1[4 * i + 1], l1[4 * i + 2], l1[4 * i + 3]);
        }

        // fold into level l+2 (2 x-texels per row-pair-pair)
        float cur2[6];
#pragma unroll
        for (int k = 0; k < 2; k++)
#pragma unroll
            for (int c = 0; c < 3; c++)
                cur2[3 * k + c] = l1[6 * k + c] + l1[6 * k + 3 + c];

        if ((p & 1) == 0) {
#pragma unroll
            for (int i = 0; i < 6; i++) acc2[i] = cur2[i];
        } else {
            float l2[6];
#pragma unroll
            for (int i = 0; i < 6; i++) l2[i] = 0.25f * (acc2[i] + cur2[i]);
            // write level l+2 row (2*yc + p/2), cols 2*xc..2*xc+1 (3 float2)
            float2* ob = (float2*)(g_mips + off_b + ((2 * yc + (p >> 1)) * w_b + 2 * xc) * 3);
            ob[0] = make_float2(l2[0], l2[1]);
            ob[1] = make_float2(l2[2], l2[3]);
            ob[2] = make_float2(l2[4], l2[5]);
#pragma unroll
            for (int c = 0; c < 3; c++) acc3[c] += l2[c] + l2[3 + c];
        }
    }

    // level l+3 texel (scalar stores; 12B stride not alignable)
    float* oc = g_mips + off_c + idx * 3;
    oc[0] = 0.25f * acc3[0];
    oc[1] = 0.25f * acc3[1];
    oc[2] = 0.25f * acc3[2];
}

// ---------------------------------------------------------------------------
// Fused 2-level downsample for levels 7,8 (input level 6: 64x64). One thread
// per level-8 texel (16x16 = 256 threads, single block).
// ---------------------------------------------------------------------------
__global__ void mip2(int in_off, int off_a, int off_b, int w_in, int shift_b)
{
    int w_b = w_in >> 2;
    int idx = blockIdx.x * blockDim.x + threadIdx.x;
    if (idx >= w_b * w_b) return;
    int xb = idx & (w_b - 1);
    int yb = idx >> shift_b;

    const float* in = g_mips + in_off;
    int rs_in = 3 * w_in;
    int w_a = w_in >> 1;

    float acc[3] = {0.f, 0.f, 0.f};
#pragma unroll
    for (int p = 0; p < 2; p++) {
        const float4* r0 = (const float4*)(in + (4 * yb + 2 * p) * rs_in + 12 * xb);
        const float4* r1 = (const float4*)((const float*)r0 + rs_in);
        float s[12];
#pragma unroll
        for (int i = 0; i < 3; i++) {
            float4 a = r0[i];
            float4 b = r1[i];
            s[4 * i + 0] = a.x + b.x;
            s[4 * i + 1] = a.y + b.y;
            s[4 * i + 2] = a.z + b.z;
            s[4 * i + 3] = a.w + b.w;
        }
        float l1[6];
#pragma unroll
        for (int j = 0; j < 2; j++)
#pragma unroll
            for (int c = 0; c < 3; c++)
                l1[3 * j + c] = 0.25f * (s[6 * j + c] + s[6 * j + 3 + c]);
        float2* oa = (float2*)(g_mips + off_a + ((2 * yb + p) * w_a + 2 * xb) * 3);
        oa[0] = make_float2(l1[0], l1[1]);
        oa[1] = make_float2(l1[2], l1[3]);
        oa[2] = make_float2(l1[4], l1[5]);
#pragma unroll
        for (int c = 0; c < 3; c++) acc[c] += l1[c] + l1[3 + c];
    }
    float* ob = g_mips + off_b + idx * 3;
    ob[0] = 0.25f * acc[0];
    ob[1] = 0.25f * acc[1];
    ob[2] = 0.25f * acc[2];
}

// ---------------------------------------------------------------------------
// Bilinear sample with wrap addressing on a square power-of-two level.
// ---------------------------------------------------------------------------
struct F3 { float x, y, z; };

__device__ __forceinline__ F3 bilin_wrap(const float* __restrict__ t, int w,
                                         float u, float v)
{
    float xs = u * (float)w - 0.5f;
    float ys = v * (float)w - 0.5f;
    float xf = floorf(xs);
    float yf = floorf(ys);
    float fx = xs - xf;
    float fy = ys - yf;
    int m = w - 1;
    int x0 = ((int)xf) & m;
    int y0 = ((int)yf) & m;
    int x1 = (x0 + 1) & m;
    int y1 = (y0 + 1) & m;

    const float* p00 = t + ((size_t)y0 * w + x0) * 3;
    const float* p01 = t + ((size_t)y0 * w + x1) * 3;
    const float* p10 = t + ((size_t)y1 * w + x0) * 3;
    const float* p11 = t + ((size_t)y1 * w + x1) * 3;

    F3 r;
#pragma unroll
    for (int c = 0; c < 3; c++) {
        float top = p00[c] + fx * (p01[c] - p00[c]);
        float bot = p10[c] + fx * (p11[c] - p10[c]);
        float val = top + fy * (bot - top);
        if (c == 0) r.x = val; else if (c == 1) r.y = val; else r.z = val;
    }
    return r;
}

// ---------------------------------------------------------------------------
// Main sample pass: one thread per output pixel.
// ---------------------------------------------------------------------------
__global__ void vt_sample(const float* __restrict__ base,
                          const float2* __restrict__ texc,
                          const float4* __restrict__ deriv,
                          float* __restrict__ out)
{
    int idx = blockIdx.x * blockDim.x + threadIdx.x;
    if (idx >= OUT_W * OUT_W) return;

    float4 d = deriv[idx];
    float dudx = d.x * (float)BASE_W;
    float dvdx = d.y * (float)BASE_W;
    float dudy = d.z * (float)BASE_W;
    float dvdy = d.w * (float)BASE_W;
    float rho2 = fmaxf(dudx * dudx + dvdx * dvdx, dudy * dudy + dvdy * dvdy);
    float lod = 0.5f * __log2f(fmaxf(rho2, 1e-20f));
    lod = fminf(fmaxf(lod, 0.0f), (float)MAX_MIP);

    int l0 = min((int)lod, MAX_MIP);
    float fr = lod - (float)l0;
    int l1 = min(l0 + 1, MAX_MIP);

    float2 uv = texc[idx];

    const float* t0 = (l0 == 0) ? base : (g_mips + c_mip_off[l0]);
    F3 a = bilin_wrap(t0, BASE_W >> l0, uv.x, uv.y);

    const float* t1 = (l1 == 0) ? base : (g_mips + c_mip_off[l1]);
    F3 b = bilin_wrap(t1, BASE_W >> l1, uv.x, uv.y);

    float* o = out + (size_t)idx * 3;
    o[0] = a.x + fr * (b.x - a.x);
    o[1] = a.y + fr * (b.y - a.y);
    o[2] = a.z + fr * (b.z - a.z);
}

// ---------------------------------------------------------------------------
extern "C" void kernel_launch(void* const* d_in, const int* in_sizes, int n_in,
                              void* d_out, int out_size)
{
    const float*  data  = (const float*)d_in[0];
    const float2* texc  = (const float2*)d_in[1];
    const float4* deriv = (const float4*)d_in[2];
    float* out = (float*)d_out;

    static const int off_h[9] = {
        0, 0, 12582912, 15728640, 16515072, 16711680, 16760832, 16773120, 16776192
    };

    const int TPB = 256;

    // Levels 1-3 from base: 512^2 threads, each over an 8x8 base region.
    {
        int n = 512 * 512;
        mip3<<<(n + TPB - 1) / TPB, TPB>>>(data, -1,
                                           off_h[1], off_h[2], off_h[3],
                                           BASE_W, 9);
    }
    // Levels 4-6 from level 3: 64^2 threads.
    {
        int n = 64 * 64;
        mip3<<<(n + TPB - 1) / TPB, TPB>>>(data, off_h[3],
                                           off_h[4], off_h[5], off_h[6],
                                           512, 6);
    }
    // Levels 7-8 from level 6: 16^2 threads.
    {
        mip2<<<1, 256>>>(off_h[6], off_h[7], off_h[8], 64, 4);
    }

    // Sample pass
    {
        int n = OUT_W * OUT_W;
        vt_sample<<<(n + TPB - 1) / TPB, TPB>>>(data, texc, deriv, out);
    }
}

// round 5
// speedup vs baseline: 1.2984x; 1.0413x over previous
#include <cuda_runtime.h>

// ---------------------------------------------------------------------------
// VirtualTextureModule: trilinear mip-mapped texture sampling (wrap mode).
//  data: [1,4096,4096,3] f32, texc: [1,1024,1024,2], texc_deriv: [1,1024,1024,4]
//  out:  [1,1024,1024,3] f32
//
// R5: pad mip levels 2..8 to float4 texels (RGBx) so each bilinear corner in
// the (random-gather, L1tex-bound) sample pass is one LDG.128 instead of
// 3 scalar LDGs. Level 1 stays unpadded (rare lod<2 tail uses scalar path;
// avoids +17MB write on the bandwidth-critical first mip kernel).
// ---------------------------------------------------------------------------

#define BASE_W   4096
#define OUT_W    1024
#define MAX_MIP  8

// Layout of g_mips (float units):
//  L1 unpadded RGB : off 0,        size 2048^2*3 = 12,582,912
//  L2 padded RGBx  : off 12582912, size 1024^2*4 =  4,194,304
//  L3 padded       : off 16777216, size  512^2*4 =  1,048,576
//  L4 padded       : off 17825792, size  256^2*4 =    262,144
//  L5 padded       : off 18087936, size  128^2*4 =     65,536
//  L6 padded       : off 18153472, size   64^2*4 =     16,384
//  L7 padded       : off 18169856, size   32^2*4 =      4,096
//  L8 padded       : off 18173952, size   16^2*4 =      1,024
__device__ float g_mips[18174976];

// float4-unit offsets of padded levels 2..8 (index l-2 unused slots kept simple)
__constant__ int c_pad_q[9] = {
    0, 0,
    3145728,   // L2
    4194304,   // L3
    4456448,   // L4
    4521984,   // L5
    4538368,   // L6
    4542464,   // L7
    4543488    // L8
};

// ---------------------------------------------------------------------------
// Kernel 1: base (unpadded RGB) -> L1 (unpadded RGB), L2 (padded), L3 (padded).
// One thread = one L3 texel from an 8x8 base region.
// ---------------------------------------------------------------------------
__global__ void mip3_base(const float* __restrict__ base,
                          int off1 /*float*/, int off2q, int off3q /*float4*/,
                          int w_in, int shift_c)
{
    int w_c = w_in >> 3;                 // 512
    int n = w_c * w_c;
    int idx = blockIdx.x * blockDim.x + threadIdx.x;
    if (idx >= n) return;
    int xc = idx & (w_c - 1);
    int yc = idx >> shift_c;

    int rs_in = 3 * w_in;
    int w_a = w_in >> 1;                 // L1 width
    int w_b = w_in >> 2;                 // L2 width
    float4* pad = (float4*)g_mips;

    float acc2[6];
    float acc3[3] = {0.f, 0.f, 0.f};

#pragma unroll
    for (int p = 0; p < 4; p++) {
        const float4* r0 = (const float4*)(base + (8 * yc + 2 * p) * rs_in + 24 * xc);
        const float4* r1 = (const float4*)((const float*)r0 + rs_in);

        float s[24];
#pragma unroll
        for (int i = 0; i < 6; i++) {
            float4 a = r0[i];
            float4 b = r1[i];
            s[4 * i + 0] = a.x + b.x;
            s[4 * i + 1] = a.y + b.y;
            s[4 * i + 2] = a.z + b.z;
            s[4 * i + 3] = a.w + b.w;
        }

        float l1v[12];
#pragma unroll
        for (int j = 0; j < 4; j++)
#pragma unroll
            for (int c = 0; c < 3; c++)
                l1v[3 * j + c] = 0.25f * (s[6 * j + c] + s[6 * j + 3 + c]);

        // L1 (unpadded): row 4yc+p, cols 4xc..4xc+3 -> 3 aligned float4
        {
            float4* oa = (float4*)(g_mips + off1 + ((4 * yc + p) * w_a + 4 * xc) * 3);
#pragma unroll
            for (int i = 0; i < 3; i++)
                oa[i] = make_float4(l1v[4 * i], l1v[4 * i + 1], l1v[4 * i + 2], l1v[4 * i + 3]);
        }

        float cur2[6];
#pragma unroll
        for (int k = 0; k < 2; k++)
#pragma unroll
            for (int c = 0; c < 3; c++)
                cur2[3 * k + c] = l1v[6 * k + c] + l1v[6 * k + 3 + c];

        if ((p & 1) == 0) {
#pragma unroll
            for (int i = 0; i < 6; i++) acc2[i] = cur2[i];
        } else {
            float l2v[6];
#pragma unroll
            for (int i = 0; i < 6; i++) l2v[i] = 0.25f * (acc2[i] + cur2[i]);
            // L2 padded: row 2yc+p/2, cols 2xc,2xc+1 -> 2 consecutive float4
            float4* ob = pad + off2q + (2 * yc + (p >> 1)) * w_b + 2 * xc;
            ob[0] = make_float4(l2v[0], l2v[1], l2v[2], 0.f);
            ob[1] = make_float4(l2v[3], l2v[4], l2v[5], 0.f);
#pragma unroll
            for (int c = 0; c < 3; c++) acc3[c] += l2v[c] + l2v[3 + c];
        }
    }

    pad[off3q + idx] = make_float4(0.25f * acc3[0], 0.25f * acc3[1], 0.25f * acc3[2], 0.f);
}

// ---------------------------------------------------------------------------
// Kernel 2: padded -> 3 padded levels. One thread = one L+3 texel from 8x8.
// ---------------------------------------------------------------------------
__global__ void mip3_pad(int inq, int offaq, int offbq, int offcq,
                         int w_in, int shift_c)
{
    int w_c = w_in >> 3;
    int n = w_c * w_c;
    int idx = blockIdx.x * blockDim.x + threadIdx.x;
    if (idx >= n) return;
    int xc = idx & (w_c - 1);
    int yc = idx >> shift_c;

    float4* pad = (float4*)g_mips;
    const float4* in = pad + inq;
    int w_a = w_in >> 1;
    int w_b = w_in >> 2;

    float4 acc2[2];
    float3 acc3 = make_float3(0.f, 0.f, 0.f);

#pragma unroll
    for (int p = 0; p < 4; p++) {
        const float4* r0 = in + (8 * yc + 2 * p) * w_in + 8 * xc;
        const float4* r1 = r0 + w_in;

        float4 l1v[4];
#pragma unroll
        for (int j = 0; j < 4; j++) {
            float4 a0 = r0[2 * j],     b0 = r1[2 * j];
            float4 a1 = r0[2 * j + 1], b1 = r1[2 * j + 1];
            l1v[j] = make_float4(0.25f * (a0.x + b0.x + a1.x + b1.x),
                                 0.25f * (a0.y + b0.y + a1.y + b1.y),
                                 0.25f * (a0.z + b0.z + a1.z + b1.z), 0.f);
        }
        // write 4 consecutive float4
        {
            float4* oa = pad + offaq + (4 * yc + p) * w_a + 4 * xc;
#pragma unroll
            for (int j = 0; j < 4; j++) oa[j] = l1v[j];
        }

        float4 cur2[2];
#pragma unroll
        for (int k = 0; k < 2; k++)
            cur2[k] = make_float4(l1v[2 * k].x + l1v[2 * k + 1].x,
                                  l1v[2 * k].y + l1v[2 * k + 1].y,
                                  l1v[2 * k].z + l1v[2 * k + 1].z, 0.f);

        if ((p & 1) == 0) {
            acc2[0] = cur2[0]; acc2[1] = cur2[1];
        } else {
            float4* ob = pad + offbq + (2 * yc + (p >> 1)) * w_b + 2 * xc;
            float4 l2v[2];
#pragma unroll
            for (int k = 0; k < 2; k++) {
                l2v[k] = make_float4(0.25f * (acc2[k].x + cur2[k].x),
                                     0.25f * (acc2[k].y + cur2[k].y),
                                     0.25f * (acc2[k].z + cur2[k].z), 0.f);
                ob[k] = l2v[k];
            }
            acc3.x += l2v[0].x + l2v[1].x;
            acc3.y += l2v[0].y + l2v[1].y;
            acc3.z += l2v[0].z + l2v[1].z;
        }
    }

    pad[offcq + idx] = make_float4(0.25f * acc3.x, 0.25f * acc3.y, 0.25f * acc3.z, 0.f);
}

// ---------------------------------------------------------------------------
// Kernel 3: padded 2-level downsample (L6 -> L7, L8). 256 threads.
// ---------------------------------------------------------------------------
__global__ void mip2_pad(int inq, int offaq, int offbq, int w_in, int shift_b)
{
    int w_b = w_in >> 2;
    int idx = blockIdx.x * blockDim.x + threadIdx.x;
    if (idx >= w_b * w_b) return;
    int xb = idx & (w_b - 1);
    int yb = idx >> shift_b;

    float4* pad = (float4*)g_mips;
    const float4* in = pad + inq;
    int w_a = w_in >> 1;

    float3 acc = make_float3(0.f, 0.f, 0.f);
#pragma unroll
    for (int p = 0; p < 2; p++) {
        const float4* r0 = in + (4 * yb + 2 * p) * w_in + 4 * xb;
        const float4* r1 = r0 + w_in;
        float4 l1v[2];
#pragma unroll
        for (int j = 0; j < 2; j++) {
            float4 a0 = r0[2 * j],     b0 = r1[2 * j];
            float4 a1 = r0[2 * j + 1], b1 = r1[2 * j + 1];
            l1v[j] = make_float4(0.25f * (a0.x + b0.x + a1.x + b1.x),
                                 0.25f * (a0.y + b0.y + a1.y + b1.y),
                                 0.25f * (a0.z + b0.z + a1.z + b1.z), 0.f);
        }
        float4* oa = pad + offaq + (2 * yb + p) * w_a + 2 * xb;
        oa[0] = l1v[0];
        oa[1] = l1v[1];
        acc.x += l1v[0].x + l1v[1].x;
        acc.y += l1v[0].y + l1v[1].y;
        acc.z += l1v[0].z + l1v[1].z;
    }
    pad[offbq + idx] = make_float4(0.25f * acc.x, 0.25f * acc.y, 0.25f * acc.z, 0.f);
}

// ---------------------------------------------------------------------------
// Bilinear samplers
// ---------------------------------------------------------------------------
struct F3 { float x, y, z; };

// scalar RGB (levels 0 and 1)
__device__ __forceinline__ F3 bilin_wrap(const float* __restrict__ t, int w,
                                         float u, float v)
{
    float xs = u * (float)w - 0.5f;
    float ys = v * (float)w - 0.5f;
    float xf = floorf(xs);
    float yf = floorf(ys);
    float fx = xs - xf;
    float fy = ys - yf;
    int m = w - 1;
    int x0 = ((int)xf) & m;
    int y0 = ((int)yf) & m;
    int x1 = (x0 + 1) & m;
    int y1 = (y0 + 1) & m;

    const float* p00 = t + ((size_t)y0 * w + x0) * 3;
    const float* p01 = t + ((size_t)y0 * w + x1) * 3;
    const float* p10 = t + ((size_t)y1 * w + x0) * 3;
    const float* p11 = t + ((size_t)y1 * w + x1) * 3;

    F3 r;
#pragma unroll
    for (int c = 0; c < 3; c++) {
        float top = p00[c] + fx * (p01[c] - p00[c]);
        float bot = p10[c] + fx * (p11[c] - p10[c]);
        float val = top + fy * (bot - top);
        if (c == 0) r.x = val; else if (c == 1) r.y = val; else r.z = val;
    }
    return r;
}

// padded float4 (levels 2..8): 4x LDG.128
__device__ __forceinline__ F3 bilin_wrap_pad(const float4* __restrict__ t, int w,
                                             float u, float v)
{
    float xs = u * (float)w - 0.5f;
    float ys = v * (float)w - 0.5f;
    float xf = floorf(xs);
    float yf = floorf(ys);
    float fx = xs - xf;
    float fy = ys - yf;
    int m = w - 1;
    int x0 = ((int)xf) & m;
    int y0 = ((int)yf) & m;
    int x1 = (x0 + 1) & m;
    int y1 = (y0 + 1) & m;

    float4 p00 = t[y0 * w + x0];
    float4 p01 = t[y0 * w + x1];
    float4 p10 = t[y1 * w + x0];
    float4 p11 = t[y1 * w + x1];

    F3 r;
    float tx, bx;
    tx = p00.x + fx * (p01.x - p00.x);
    bx = p10.x + fx * (p11.x - p10.x);
    r.x = tx + fy * (bx - tx);
    tx = p00.y + fx * (p01.y - p00.y);
    bx = p10.y + fx * (p11.y - p10.y);
    r.y = tx + fy * (bx - tx);
    tx = p00.z + fx * (p01.z - p00.z);
    bx = p10.z + fx * (p11.z - p10.z);
    r.z = tx + fy * (bx - tx);
    return r;
}

__device__ __forceinline__ F3 sample_level(const float* __restrict__ base,
                                           int l, float u, float v)
{
    if (l >= 2) {
        return bilin_wrap_pad((const float4*)g_mips + c_pad_q[l], BASE_W >> l, u, v);
    } else if (l == 1) {
        return bilin_wrap(g_mips, BASE_W >> 1, u, v);
    } else {
        return bilin_wrap(base, BASE_W, u, v);
    }
}

// ---------------------------------------------------------------------------
// Main sample pass: one thread per output pixel.
// ---------------------------------------------------------------------------
__global__ void vt_sample(const float* __restrict__ base,
                          const float2* __restrict__ texc,
                          const float4* __restrict__ deriv,
                          float* __restrict__ out)
{
    int idx = blockIdx.x * blockDim.x + threadIdx.x;
    if (idx >= OUT_W * OUT_W) return;

    float4 d = deriv[idx];
    float dudx = d.x * (float)BASE_W;
    float dvdx = d.y * (float)BASE_W;
    float dudy = d.z * (float)BASE_W;
    float dvdy = d.w * (float)BASE_W;
    float rho2 = fmaxf(dudx * dudx + dvdx * dvdx, dudy * dudy + dvdy * dvdy);
    float lod = 0.5f * __log2f(fmaxf(rho2, 1e-20f));
    lod = fminf(fmaxf(lod, 0.0f), (float)MAX_MIP);

    int l0 = min((int)lod, MAX_MIP);
    float fr = lod - (float)l0;
    int l1 = min(l0 + 1, MAX_MIP);

    float2 uv = texc[idx];

    F3 a, b;
    if (l0 >= 2) {
        // fast path: both levels padded (common: lod in [3,4.5])
        a = bilin_wrap_pad((const float4*)g_mips + c_pad_q[l0], BASE_W >> l0, uv.x, uv.y);
        b = bilin_wrap_pad((const float4*)g_mips + c_pad_q[l1], BASE_W >> l1, uv.x, uv.y);
    } else {
        a = sample_level(base, l0, uv.x, uv.y);
        b = sample_level(base, l1, uv.x, uv.y);
    }

    float* o = out + (size_t)idx * 3;
    o[0] = a.x + fr * (b.x - a.x);
    o[1] = a.y + fr * (b.y - a.y);
    o[2] = a.z + fr * (b.z - a.z);
}

// ---------------------------------------------------------------------------
extern "C" void kernel_launch(void* const* d_in, const int* in_sizes, int n_in,
                              void* d_out, int out_size)
{
    const float*  data  = (const float*)d_in[0];
    const float2* texc  = (const float2*)d_in[1];
    const float4* deriv = (const float4*)d_in[2];
    float* out = (float*)d_out;

    // float4-unit offsets (host copies of c_pad_q)
    const int L2q = 3145728, L3q = 4194304, L4q = 4456448, L5q = 4521984;
    const int L6q = 4538368, L7q = 4542464, L8q = 4543488;

    const int TPB = 256;

    // Levels 1-3 from base: 512^2 threads over 8x8 base regions.
    {
        int n = 512 * 512;
        mip3_base<<<(n + TPB - 1) / TPB, TPB>>>(data, 0, L2q, L3q, BASE_W, 9);
    }
    // Levels 4-6 from padded L3: 64^2 threads.
    {
        int n = 64 * 64;
        mip3_pad<<<(n + TPB - 1) / TPB, TPB>>>(L3q, L4q, L5q, L6q, 512, 6);
    }
    // Levels 7-8 from padded L6: 16^2 threads.
    mip2_pad<<<1, 256>>>(L6q, L7q, L8q, 64, 4);

    // Sample pass
    {
        int n = OUT_W * OUT_W;
        vt_sample<<<(n + TPB - 1) / TPB, TPB>>>(data, texc, deriv, out);
    }
}

// round 6
// speedup vs baseline: 1.3886x; 1.0694x over previous
#include <cuda_runtime.h>

// ---------------------------------------------------------------------------
// VirtualTextureModule: trilinear mip-mapped texture sampling (wrap mode).
//  data: [1,4096,4096,3] f32, texc: [1,1024,1024,2], texc_deriv: [1,1024,1024,4]
//  out:  [1,1024,1024,3] f32
//
// R6: texel-PAIR storage for mip levels 2..8. Pair (y,x) = [texel x | texel
// (x+1)%w], 32 bytes, wrap pre-baked. Sampling a bilinear tap = two 256-bit
// loads (ld.global.v8.b32) instead of four 128-bit gathers. Level 1 is no
// longer materialized: the rare lod<2 tail computes L1 texels from base.
// ---------------------------------------------------------------------------

#define BASE_W   4096
#define OUT_W    1024
#define MAX_MIP  8

// Paired levels 2..8: level l (w=4096>>l) occupies w*w pairs * 8 floats.
//  L2: off 0          (1024^2*8 = 8,388,608)
//  L3: off 8388608    ( 512^2*8 = 2,097,152)
//  L4: off 10485760   ( 256^2*8 =   524,288)
//  L5: off 11010048   ( 128^2*8 =   131,072)
//  L6: off 11141120   (  64^2*8 =    32,768)
//  L7: off 11173888   (  32^2*8 =     8,192)
//  L8: off 11182080   (  16^2*8 =     2,048)
__device__ __align__(128) float g_pairs[11184128];

__constant__ int c_pair_off[9] = {
    0, 0, 0, 8388608, 10485760, 11010048, 11141120, 11173888, 11182080
};

// 256-bit global load (sm_100+): 8 x b32.
__device__ __forceinline__ void ldg_v8(const float* __restrict__ p, float* r)
{
    unsigned u0, u1, u2, u3, u4, u5, u6, u7;
    asm("ld.global.v8.b32 {%0,%1,%2,%3,%4,%5,%6,%7}, [%8];"
        : "=r"(u0), "=r"(u1), "=r"(u2), "=r"(u3),
          "=r"(u4), "=r"(u5), "=r"(u6), "=r"(u7)
        : "l"(p));
    r[0] = __uint_as_float(u0); r[1] = __uint_as_float(u1);
    r[2] = __uint_as_float(u2); r[3] = __uint_as_float(u3);
    r[4] = __uint_as_float(u4); r[5] = __uint_as_float(u5);
    r[6] = __uint_as_float(u6); r[7] = __uint_as_float(u7);
}

// Paired store helpers: texel t at (x,y) on level of width w goes to
//   slot0 of pair (y*w + x)            (floats 0..2)
//   slot1 of pair (y*w + (x-1)&(w-1))  (floats 4..6)
// Each slot is written by exactly one thread.
__device__ __forceinline__ void store_pair_tex(float* lvl, int w, int x, int y,
                                               float r, float g, float b)
{
    int row = y * w;
    ((float4*)(lvl + (size_t)(row + x) * 8))[0] = make_float4(r, g, b, 0.f);
    int xm = (x - 1) & (w - 1);
    ((float4*)(lvl + (size_t)(row + xm) * 8 + 4))[0] = make_float4(r, g, b, 0.f);
}

// ---------------------------------------------------------------------------
// Kernel 1: base RGB -> paired L2, L3 (L1 computed in-register, not stored).
// One thread = one L3 texel from an 8x8 base region. 512^2 threads.
// ---------------------------------------------------------------------------
__global__ void mip3_base(const float* __restrict__ base)
{
    const int w_c = 512;
    int idx = blockIdx.x * blockDim.x + threadIdx.x;
    if (idx >= w_c * w_c) return;
    int xc = idx & (w_c - 1);
    int yc = idx >> 9;

    const int rs_in = 3 * BASE_W;        // 12288 floats per base row
    const int w2 = 1024;
    float* L2 = g_pairs;                 // offset 0
    float* L3 = g_pairs + 8388608;

    float acc2[6];
    float acc3[3] = {0.f, 0.f, 0.f};

#pragma unroll
    for (int p = 0; p < 4; p++) {
        const float4* r0 = (const float4*)(base + (size_t)(8 * yc + 2 * p) * rs_in + 24 * xc);
        const float4* r1 = (const float4*)((const float*)r0 + rs_in);

        float s[24];
#pragma unroll
        for (int i = 0; i < 6; i++) {
            float4 a = r0[i];
            float4 b = r1[i];
            s[4 * i + 0] = a.x + b.x;
            s[4 * i + 1] = a.y + b.y;
            s[4 * i + 2] = a.z + b.z;
            s[4 * i + 3] = a.w + b.w;
        }

        float l1v[12];                   // 4 L1 texels (held in registers only)
#pragma unroll
        for (int j = 0; j < 4; j++)
#pragma unroll
            for (int c = 0; c < 3; c++)
                l1v[3 * j + c] = 0.25f * (s[6 * j + c] + s[6 * j + 3 + c]);

        float cur2[6];
#pragma unroll
        for (int k = 0; k < 2; k++)
#pragma unroll
            for (int c = 0; c < 3; c++)
                cur2[3 * k + c] = l1v[6 * k + c] + l1v[6 * k + 3 + c];

        if ((p & 1) == 0) {
#pragma unroll
            for (int i = 0; i < 6; i++) acc2[i] = cur2[i];
        } else {
            float l2v[6];
#pragma unroll
            for (int i = 0; i < 6; i++) l2v[i] = 0.25f * (acc2[i] + cur2[i]);
            int r2 = 2 * yc + (p >> 1);
            store_pair_tex(L2, w2, 2 * xc,     r2, l2v[0], l2v[1], l2v[2]);
            store_pair_tex(L2, w2, 2 * xc + 1, r2, l2v[3], l2v[4], l2v[5]);
#pragma unroll
            for (int c = 0; c < 3; c++) acc3[c] += l2v[c] + l2v[3 + c];
        }
    }

    store_pair_tex(L3, 512, xc, yc,
                   0.25f * acc3[0], 0.25f * acc3[1], 0.25f * acc3[2]);
}

// ---------------------------------------------------------------------------
// Kernel 2: paired L3 -> paired L4, L5, L6. One thread = one L6 texel from
// an 8x8 L3 region. 64^2 threads.
// ---------------------------------------------------------------------------
__global__ void mip3_pad()
{
    const int w_c = 64;
    int idx = blockIdx.x * blockDim.x + threadIdx.x;
    if (idx >= w_c * w_c) return;
    int xc = idx & (w_c - 1);
    int yc = idx >> 6;

    const int w_in = 512;
    const float* IN = g_pairs + 8388608;     // L3 pairs
    float* L4 = g_pairs + 10485760;
    float* L5 = g_pairs + 11010048;
    float* L6 = g_pairs + 11141120;

    float acc2[6];
    float acc3[3] = {0.f, 0.f, 0.f};

#pragma unroll
    for (int p = 0; p < 4; p++) {
        int r0 = 8 * yc + 2 * p;
        // 8 texels per row via 4 v8 loads (pairs at even columns), 2 rows
        float t0[4][8], t1[4][8];
#pragma unroll
        for (int k = 0; k < 4; k++) {
            ldg_v8(IN + (size_t)(r0 * w_in + 8 * xc + 2 * k) * 8, t0[k]);
            ldg_v8(IN + (size_t)((r0 + 1) * w_in + 8 * xc + 2 * k) * 8, t1[k]);
        }
        // s[j][c]: vertical sums of 8 columns
        float s[8][3];
#pragma unroll
        for (int k = 0; k < 4; k++)
#pragma unroll
            for (int c = 0; c < 3; c++) {
                s[2 * k][c]     = t0[k][c]     + t1[k][c];
                s[2 * k + 1][c] = t0[k][4 + c] + t1[k][4 + c];
            }
        // 4 L4 texels
        float l1v[4][3];
#pragma unroll
        for (int j = 0; j < 4; j++)
#pragma unroll
            for (int c = 0; c < 3; c++)
                l1v[j][c] = 0.25f * (s[2 * j][c] + s[2 * j + 1][c]);
        int ra = 4 * yc + p;
#pragma unroll
        for (int j = 0; j < 4; j++)
            store_pair_tex(L4, 256, 4 * xc + j, ra, l1v[j][0], l1v[j][1], l1v[j][2]);

        float cur2[6];
#pragma unroll
        for (int k = 0; k < 2; k++)
#pragma unroll
            for (int c = 0; c < 3; c++)
                cur2[3 * k + c] = l1v[2 * k][c] + l1v[2 * k + 1][c];

        if ((p & 1) == 0) {
#pragma unroll
            for (int i = 0; i < 6; i++) acc2[i] = cur2[i];
        } else {
            float l2v[6];
#pragma unroll
            for (int i = 0; i < 6; i++) l2v[i] = 0.25f * (acc2[i] + cur2[i]);
            int rb = 2 * yc + (p >> 1);
            store_pair_tex(L5, 128, 2 * xc,     rb, l2v[0], l2v[1], l2v[2]);
            store_pair_tex(L5, 128, 2 * xc + 1, rb, l2v[3], l2v[4], l2v[5]);
#pragma unroll
            for (int c = 0; c < 3; c++) acc3[c] += l2v[c] + l2v[3 + c];
        }
    }

    store_pair_tex(L6, 64, xc, yc,
                   0.25f * acc3[0], 0.25f * acc3[1], 0.25f * acc3[2]);
}

// ---------------------------------------------------------------------------
// Kernel 3: paired L6 -> paired L7, L8. 16^2 threads, one block.
// ---------------------------------------------------------------------------
__global__ void mip2_pad()
{
    int idx = blockIdx.x * blockDim.x + threadIdx.x;
    if (idx >= 256) return;
    int xb = idx & 15;
    int yb = idx >> 4;

    const int w_in = 64;
    const float* IN = g_pairs + 11141120;    // L6 pairs
    float* L7 = g_pairs + 11173888;
    float* L8 = g_pairs + 11182080;

    float acc[3] = {0.f, 0.f, 0.f};
#pragma unroll
    for (int p = 0; p < 2; p++) {
        int r0 = 4 * yb + 2 * p;
        float t0[2][8], t1[2][8];
#pragma unroll
        for (int k = 0; k < 2; k++) {
            ldg_v8(IN + (size_t)(r0 * w_in + 4 * xb + 2 * k) * 8, t0[k]);
            ldg_v8(IN + (size_t)((r0 + 1) * w_in + 4 * xb + 2 * k) * 8, t1[k]);
        }
        float l1v[2][3];
#pragma unroll
        for (int k = 0; k < 2; k++)
#pragma unroll
            for (int c = 0; c < 3; c++)
                l1v[k][c] = 0.25f * (t0[k][c] + t0[k][4 + c] + t1[k][c] + t1[k][4 + c]);
        int ra = 2 * yb + p;
        store_pair_tex(L7, 32, 2 * xb,     ra, l1v[0][0], l1v[0][1], l1v[0][2]);
        store_pair_tex(L7, 32, 2 * xb + 1, ra, l1v[1][0], l1v[1][1], l1v[1][2]);
#pragma unroll
        for (int c = 0; c < 3; c++) acc[c] += l1v[0][c] + l1v[1][c];
    }
    store_pair_tex(L8, 16, xb, yb, 0.25f * acc[0], 0.25f * acc[1], 0.25f * acc[2]);
}

// ---------------------------------------------------------------------------
// Samplers
// ---------------------------------------------------------------------------
struct F3 { float x, y, z; };

// Paired-level bilinear (levels 2..8): two 256-bit loads.
__device__ __forceinline__ F3 bilin_pair(int off, int w, float u, float v)
{
    float xs = u * (float)w - 0.5f;
    float ys = v * (float)w - 0.5f;
    float xf = floorf(xs);
    float yf = floorf(ys);
    float fx = xs - xf;
    float fy = ys - yf;
    int m = w - 1;
    int x0 = ((int)xf) & m;
    int y0 = ((int)yf) & m;
    int y1 = (y0 + 1) & m;

    const float* P = g_pairs + off;
    float r0[8], r1[8];
    ldg_v8(P + (size_t)(y0 * w + x0) * 8, r0);   // texels (x0,y0),(x1,y0)
    ldg_v8(P + (size_t)(y1 * w + x0) * 8, r1);   // texels (x0,y1),(x1,y1)

    F3 res;
    float t, b;
    t = r0[0] + fx * (r0[4] - r0[0]);
    b = r1[0] + fx * (r1[4] - r1[0]);
    res.x = t + fy * (b - t);
    t = r0[1] + fx * (r0[5] - r0[1]);
    b = r1[1] + fx * (r1[5] - r1[1]);
    res.y = t + fy * (b - t);
    t = r0[2] + fx * (r0[6] - r0[2]);
    b = r1[2] + fx * (r1[6] - r1[2]);
    res.z = t + fy * (b - t);
    return res;
}

// Level-0 bilinear on the unpadded base texture.
__device__ __forceinline__ F3 bilin_base(const float* __restrict__ t,
                                         float u, float v)
{
    const int w = BASE_W;
    float xs = u * (float)w - 0.5f;
    float ys = v * (float)w - 0.5f;
    float xf = floorf(xs);
    float yf = floorf(ys);
    float fx = xs - xf;
    float fy = ys - yf;
    int m = w - 1;
    int x0 = ((int)xf) & m;
    int y0 = ((int)yf) & m;
    int x1 = (x0 + 1) & m;
    int y1 = (y0 + 1) & m;

    const float* p00 = t + ((size_t)y0 * w + x0) * 3;
    const float* p01 = t + ((size_t)y0 * w + x1) * 3;
    const float* p10 = t + ((size_t)y1 * w + x0) * 3;
    const float* p11 = t + ((size_t)y1 * w + x1) * 3;

    F3 r;
#pragma unroll
    for (int c = 0; c < 3; c++) {
        float top = p00[c] + fx * (p01[c] - p00[c]);
        float bot = p10[c] + fx * (p11[c] - p10[c]);
        float val = top + fy * (bot - top);
        if (c == 0) r.x = val; else if (c == 1) r.y = val; else r.z = val;
    }
    return r;
}

// On-the-fly L1 texel from base: 2x2 box of base texels (identical arithmetic
// to the reference's mip build).
__device__ __forceinline__ F3 fetch_l1(const float* __restrict__ base,
                                       int x, int y)
{
    const float* p0 = base + ((size_t)(2 * y) * BASE_W + 2 * x) * 3;
    const float* p1 = p0 + (size_t)BASE_W * 3;
    F3 r;
    r.x = 0.25f * (p0[0] + p0[3] + p1[0] + p1[3]);
    r.y = 0.25f * (p0[1] + p0[4] + p1[1] + p1[4]);
    r.z = 0.25f * (p0[2] + p0[5] + p1[2] + p1[5]);
    return r;
}

// Level-1 bilinear computed from base (rare: lod < 2 tail).
__device__ F3 bilin_l1(const float* __restrict__ base, float u, float v)
{
    const int w = BASE_W >> 1;           // 2048
    float xs = u * (float)w - 0.5f;
    float ys = v * (float)w - 0.5f;
    float xf = floorf(xs);
    float yf = floorf(ys);
    float fx = xs - xf;
    float fy = ys - yf;
    int m = w - 1;
    int x0 = ((int)xf) & m;
    int y0 = ((int)yf) & m;
    int x1 = (x0 + 1) & m;
    int y1 = (y0 + 1) & m;

    F3 p00 = fetch_l1(base, x0, y0);
    F3 p01 = fetch_l1(base, x1, y0);
    F3 p10 = fetch_l1(base, x0, y1);
    F3 p11 = fetch_l1(base, x1, y1);

    F3 r;
    float t, b;
    t = p00.x + fx * (p01.x - p00.x);
    b = p10.x + fx * (p11.x - p10.x);
    r.x = t + fy * (b - t);
    t = p00.y + fx * (p01.y - p00.y);
    b = p10.y + fx * (p11.y - p10.y);
    r.y = t + fy * (b - t);
    t = p00.z + fx * (p01.z - p00.z);
    b = p10.z + fx * (p11.z - p10.z);
    r.z = t + fy * (b - t);
    return r;
}

// ---------------------------------------------------------------------------
// Main sample pass: one thread per output pixel.
// ---------------------------------------------------------------------------
__global__ void vt_sample(const float* __restrict__ base,
                          const float2* __restrict__ texc,
                          const float4* __restrict__ deriv,
                          float* __restrict__ out)
{
    int idx = blockIdx.x * blockDim.x + threadIdx.x;
    if (idx >= OUT_W * OUT_W) return;

    float4 d = deriv[idx];
    float dudx = d.x * (float)BASE_W;
    float dvdx = d.y * (float)BASE_W;
    float dudy = d.z * (float)BASE_W;
    float dvdy = d.w * (float)BASE_W;
    float rho2 = fmaxf(dudx * dudx + dvdx * dvdx, dudy * dudy + dvdy * dvdy);
    float lod = 0.5f * __log2f(fmaxf(rho2, 1e-20f));
    lod = fminf(fmaxf(lod, 0.0f), (float)MAX_MIP);

    int l0 = min((int)lod, MAX_MIP);
    float fr = lod - (float)l0;
    int l1 = min(l0 + 1, MAX_MIP);

    float2 uv = texc[idx];

    F3 a, b;
    if (l0 >= 2) {
        // fast path (>98% of pixels): both levels paired
        a = bilin_pair(c_pair_off[l0], BASE_W >> l0, uv.x, uv.y);
        b = bilin_pair(c_pair_off[l1], BASE_W >> l1, uv.x, uv.y);
    } else if (l0 == 1) {
        a = bilin_l1(base, uv.x, uv.y);
        b = bilin_pair(c_pair_off[2], BASE_W >> 2, uv.x, uv.y);
    } else {
        a = bilin_base(base, uv.x, uv.y);
        b = bilin_l1(base, uv.x, uv.y);
    }

    float* o = out + (size_t)idx * 3;
    o[0] = a.x + fr * (b.x - a.x);
    o[1] = a.y + fr * (b.y - a.y);
    o[2] = a.z + fr * (b.z - a.z);
}

// ---------------------------------------------------------------------------
extern "C" void kernel_launch(void* const* d_in, const int* in_sizes, int n_in,
                              void* d_out, int out_size)
{
    const float*  data  = (const float*)d_in[0];
    const float2* texc  = (const float2*)d_in[1];
    const float4* deriv = (const float4*)d_in[2];
    float* out = (float*)d_out;

    const int TPB = 256;

    mip3_base<<<(512 * 512 + TPB - 1) / TPB, TPB>>>(data);
    mip3_pad<<<(64 * 64 + TPB - 1) / TPB, TPB>>>();
    mip2_pad<<<1, 256>>>();

    vt_sample<<<(OUT_W * OUT_W + TPB - 1) / TPB, TPB>>>(data, texc, deriv, out);
}